// round 1
// baseline (speedup 1.0000x reference)
#include <cuda_runtime.h>
#include <cstdint>
#include <cstddef>

// Problem constants
#define T_STEPS 512
#define DH      2048
#define DI      64
#define DO      64
#define BATCH   128
#define HC      64                 // rows of DH processed per chunk
#define NCHUNK  (DH / HC)          // 32

// Scratch (device globals; no allocations allowed)
__device__ float g_sr0[DH * BATCH];    // sigmoid(r0)
__device__ float g_base[DH * BATCH];   // (1-alpha)*r0 + alpha*(|W| @ sigmoid(r0))

// ---------- packed f32x2 helpers (Blackwell FFMA2) ----------
union F2U { unsigned long long u; float2 f; };

__device__ __forceinline__ unsigned long long pack2(float w) {
    unsigned int wi = __float_as_uint(w);
    unsigned long long r;
    asm("mov.b64 %0, {%1, %1};" : "=l"(r) : "r"(wi));
    return r;
}
__device__ __forceinline__ void fma2(unsigned long long& d,
                                     unsigned long long a,
                                     unsigned long long b) {
    asm("fma.rn.f32x2 %0, %1, %2, %0;" : "+l"(d) : "l"(a), "l"(b));
}

__device__ __forceinline__ float sigm(float x) {
    return __fdividef(1.0f, 1.0f + __expf(-x));
}

// ---------- kernel 0: sigmoid(r0) ----------
__global__ void sig_kernel(const float* __restrict__ r0) {
    int i = (blockIdx.x * blockDim.x + threadIdx.x) * 4;  // 256x256x4 = 262144
    float4 v = *(const float4*)(r0 + i);
    v.x = sigm(v.x); v.y = sigm(v.y); v.z = sigm(v.z); v.w = sigm(v.w);
    *(float4*)(g_sr0 + i) = v;
}

// ---------- kernel 1: base = (1-a)*r0 + a*(|W| @ sr0) ----------
// grid 128 blocks (16 h-rows each), 256 threads.
__global__ void __launch_bounds__(256, 2)
base_kernel(const float* __restrict__ r0,
            const float* __restrict__ w_,
            const float* __restrict__ taus) {
    extern __shared__ float sm[];
    float* sr_s = sm;              // 128 x 128 (k x b)
    float* w_s  = sm + 128 * 128;  // 16 x 128  (h x k)

    int tid = threadIdx.x;
    int cp  = tid & 31;            // column group: cols 4cp..4cp+3
    int rg  = tid >> 5;            // warp id: rows rg*2, rg*2+1
    int hbase = blockIdx.x * 16;

    unsigned long long acc[2][2] = {{0ull, 0ull}, {0ull, 0ull}};

    for (int kc = 0; kc < DH / 128; ++kc) {
        int k0 = kc * 128;
        __syncthreads();
        // load sigmoid(r0) chunk (contiguous 16384 floats)
        {
            const float4* src = (const float4*)(g_sr0 + (size_t)k0 * BATCH);
            float4* dst = (float4*)sr_s;
#pragma unroll
            for (int i = 0; i < 16; ++i) dst[tid + i * 256] = src[tid + i * 256];
        }
        // load |W| chunk: w_s[r][kk] = |w_[(hbase+r)*DH + k0+kk]|
#pragma unroll
        for (int j = 0; j < 2; ++j) {
            int e  = j * 1024 + tid * 4;
            int r  = e >> 7;
            int kk = e & 127;
            float4 wv = *(const float4*)(w_ + (size_t)(hbase + r) * DH + k0 + kk);
            wv.x = fabsf(wv.x); wv.y = fabsf(wv.y);
            wv.z = fabsf(wv.z); wv.w = fabsf(wv.w);
            *(float4*)(w_s + r * 128 + kk) = wv;
        }
        __syncthreads();

#pragma unroll 4
        for (int kk = 0; kk < 128; ++kk) {
            ulonglong2 sv = *(const ulonglong2*)(sr_s + kk * BATCH + 4 * cp);
#pragma unroll
            for (int r = 0; r < 2; ++r) {
                unsigned long long pw = pack2(w_s[(rg * 2 + r) * 128 + kk]);
                fma2(acc[r][0], pw, sv.x);
                fma2(acc[r][1], pw, sv.y);
            }
        }
    }

#pragma unroll
    for (int r = 0; r < 2; ++r) {
        int h = hbase + rg * 2 + r;
        float alpha = 1.0f / taus[h];               // DT = 1.0
        float om = 1.0f - alpha;
        float4 rv = *(const float4*)(r0 + (size_t)h * BATCH + 4 * cp);
        F2U lo, hi; lo.u = acc[r][0]; hi.u = acc[r][1];
        float4 o;
        o.x = om * rv.x + alpha * lo.f.x;
        o.y = om * rv.y + alpha * lo.f.y;
        o.z = om * rv.z + alpha * hi.f.x;
        o.w = om * rv.w + alpha * hi.f.y;
        *(float4*)(g_base + (size_t)h * BATCH + 4 * cp) = o;
    }
}

// ---------- main kernel: one block per timestep ----------
// xs[t] = base + win@u[t] + noise[t];  out[t] = wout @ sigmoid(xs[t]) + bias
__global__ void __launch_bounds__(256, 2)
main_kernel(const float* __restrict__ u,
            const float* __restrict__ noise,
            const float* __restrict__ win,
            const float* __restrict__ wout,
            const float* __restrict__ bias,
            float* __restrict__ out) {
    extern __shared__ float sm[];
    float* u_s    = sm;                   // 64 x 128
    float* win_s  = sm + DI * BATCH;      // 64 x 64   (+8192)
    float* wout_s = win_s + HC * DI;      // 64 x 64   (+12288)
    float* s_s    = wout_s + DO * HC;     // 64 x 128  (+16384)

    int tid = threadIdx.x;
    int cp  = tid & 31;                   // cols 4cp..4cp+3
    int rg  = tid >> 5;                   // warp id: rows rg*8..rg*8+7
    int t   = blockIdx.x;

    float* xsout = out + (size_t)T_STEPS * DO * BATCH;

    // stage u[t] (32 KB, contiguous)
    {
        const float4* src = (const float4*)(u + (size_t)t * DI * BATCH);
        float4* dst = (float4*)u_s;
#pragma unroll
        for (int i = 0; i < 8; ++i) dst[tid + i * 256] = src[tid + i * 256];
    }

    unsigned long long oacc[16];
#pragma unroll
    for (int i = 0; i < 16; ++i) oacc[i] = 0ull;

    for (int c = 0; c < NCHUNK; ++c) {
        int h0 = c * HC;
        __syncthreads();
        // win chunk (contiguous 4096 floats)
        {
            const float4* src = (const float4*)(win + (size_t)h0 * DI);
            float4* dst = (float4*)win_s;
#pragma unroll
            for (int i = 0; i < 4; ++i) dst[tid + i * 256] = src[tid + i * 256];
        }
        // wout chunk: wout_s[o][hh] = wout[o*DH + h0 + hh]
#pragma unroll
        for (int j = 0; j < 4; ++j) {
            int e  = j * 1024 + tid * 4;
            int o  = e >> 6;
            int hh = e & 63;
            *(float4*)(wout_s + o * HC + hh) =
                *(const float4*)(wout + (size_t)o * DH + h0 + hh);
        }
        __syncthreads();

        // ---- GEMM1: inp = win_chunk @ u[t]  (K = 64) ----
        unsigned long long a1[16];
#pragma unroll
        for (int i = 0; i < 16; ++i) a1[i] = 0ull;
#pragma unroll 4
        for (int d = 0; d < DI; ++d) {
            ulonglong2 uv = *(const ulonglong2*)(u_s + d * BATCH + 4 * cp);
#pragma unroll
            for (int j = 0; j < 8; ++j) {
                unsigned long long pw = pack2(win_s[(rg * 8 + j) * DI + d]);
                fma2(a1[2 * j],     pw, uv.x);
                fma2(a1[2 * j + 1], pw, uv.y);
            }
        }

        // ---- epilogue: xs = a1 + base + noise; write xs; s_s = sigmoid(xs) ----
#pragma unroll
        for (int j = 0; j < 8; ++j) {
            int hh = rg * 8 + j;
            int h  = h0 + hh;
            size_t gidx = ((size_t)t * DH + h) * BATCH + 4 * cp;
            float4 bs = *(const float4*)(g_base + (size_t)h * BATCH + 4 * cp);
            float4 nz = *(const float4*)(noise + gidx);
            F2U lo, hi; lo.u = a1[2 * j]; hi.u = a1[2 * j + 1];
            float4 xs;
            xs.x = lo.f.x + bs.x + nz.x;
            xs.y = lo.f.y + bs.y + nz.y;
            xs.z = hi.f.x + bs.z + nz.z;
            xs.w = hi.f.y + bs.w + nz.w;
            *(float4*)(xsout + gidx) = xs;
            float4 sv;
            sv.x = sigm(xs.x); sv.y = sigm(xs.y);
            sv.z = sigm(xs.z); sv.w = sigm(xs.w);
            *(float4*)(s_s + hh * BATCH + 4 * cp) = sv;
        }
        __syncthreads();

        // ---- GEMM2: out += wout_chunk @ s  (accumulate over chunks) ----
#pragma unroll 4
        for (int hh = 0; hh < HC; ++hh) {
            ulonglong2 sv = *(const ulonglong2*)(s_s + hh * BATCH + 4 * cp);
#pragma unroll
            for (int j = 0; j < 8; ++j) {
                unsigned long long pw = pack2(wout_s[(rg * 8 + j) * HC + hh]);
                fma2(oacc[2 * j],     pw, sv.x);
                fma2(oacc[2 * j + 1], pw, sv.y);
            }
        }
    }

    // write outputs[t]
#pragma unroll
    for (int j = 0; j < 8; ++j) {
        int o = rg * 8 + j;
        float bv = bias[o];
        F2U lo, hi; lo.u = oacc[2 * j]; hi.u = oacc[2 * j + 1];
        float4 r;
        r.x = lo.f.x + bv; r.y = lo.f.y + bv;
        r.z = hi.f.x + bv; r.w = hi.f.y + bv;
        *(float4*)(out + ((size_t)t * DO + o) * BATCH + 4 * cp) = r;
    }
}

extern "C" void kernel_launch(void* const* d_in, const int* in_sizes, int n_in,
                              void* d_out, int out_size) {
    const float* u     = (const float*)d_in[0];  // (T, DI, B)
    const float* r0    = (const float*)d_in[1];  // (DH, B)
    const float* noise = (const float*)d_in[2];  // (T, DH, B)
    const float* win   = (const float*)d_in[3];  // (DH, DI)
    const float* w_    = (const float*)d_in[4];  // (DH, DH)
    // d_in[5] = m_diag: unused — |_w * (+-1)| == |_w|
    const float* wout  = (const float*)d_in[6];  // (DO, DH)
    const float* bias  = (const float*)d_in[7];  // (DO, 1)
    const float* taus  = (const float*)d_in[8];  // (DH, 1)
    float* out = (float*)d_out;                  // outputs (T,DO,B) then xs (T,DH,B)

    const int base_smem = (128 * 128 + 16 * 128) * 4;           // 73728 B
    const int main_smem = (DI * BATCH + HC * DI + DO * HC + HC * BATCH) * 4; // 98304 B
    cudaFuncSetAttribute(base_kernel, cudaFuncAttributeMaxDynamicSharedMemorySize, base_smem);
    cudaFuncSetAttribute(main_kernel, cudaFuncAttributeMaxDynamicSharedMemorySize, main_smem);

    sig_kernel<<<256, 256>>>(r0);
    base_kernel<<<DH / 16, 256, base_smem>>>(r0, w_, taus);
    main_kernel<<<T_STEPS, 256, main_smem>>>(u, noise, win, wout, bias, out);
}